// round 11
// baseline (speedup 1.0000x reference)
#include <cuda_runtime.h>
#include <cuda_fp16.h>
#include <math.h>
#include <stdint.h>

#define BB 16
#define NN 1024
#define DD 256
#define L2E 1.4426950408889634f
#define LN2F 0.6931471805599453f

// fp16 arrays: logK * log2(e)  (log2 domain) — the ONLY K storage (64 MB total).
static __device__ __half d_logKh [BB*NN*NN];  // 32 MB
static __device__ __half d_logKTh[BB*NN*NN];  // 32 MB
// potentials in LOG2 domain
static __device__ float  d_f[BB*NN];
static __device__ float  d_g[BB*NN];
static __device__ __half d_fh[BB*NN];
static __device__ __half d_gh[BB*NN];
static __device__ float d_inx[BB*NN];
static __device__ float d_iny[BB*NN];
static __device__ float d_r[BB*NN];
static __device__ float d_c[BB*NN];
static __device__ float d_xg[BB*DD];
static __device__ float d_yg[BB*DD];
static __device__ float d_Lmain[BB];
static __device__ float d_LbX[BB];
static __device__ float d_LbY[BB];
static __device__ float d_loss[BB];
// group-barrier state: one 128B-strided slot per batch group (reset each replay)
static __device__ unsigned g_arr[16*32];
static __device__ unsigned g_ep [16*32];

__device__ __forceinline__ float warpMax(float v){
  #pragma unroll
  for (int o=16;o>0;o>>=1) v = fmaxf(v, __shfl_xor_sync(0xffffffffu, v, o));
  return v;
}
__device__ __forceinline__ float warpSum(float v){
  #pragma unroll
  for (int o=16;o>0;o>>=1) v += __shfl_xor_sync(0xffffffffu, v, o);
  return v;
}
__device__ __forceinline__ float blockSum256(float v, float* sm){
  __syncthreads();
  v = warpSum(v);
  int w = threadIdx.x>>5, l = threadIdx.x&31;
  if (l==0) sm[w]=v;
  __syncthreads();
  if (w==0){
    float t = (l<8)? sm[l] : 0.0f;
    t = warpSum(t);
    if (l==0) sm[0]=t;
  }
  __syncthreads();
  return sm[0];
}

__device__ __forceinline__ void fma2(unsigned long long& d, unsigned long long a, unsigned long long b){
  asm("fma.rn.f32x2 %0, %1, %2, %0;" : "+l"(d) : "l"(a), "l"(b));
}
__device__ __forceinline__ void unpack2(unsigned long long p, float& lo, float& hi){
  asm("mov.b64 {%0,%1}, %2;" : "=f"(lo), "=f"(hi) : "l"(p));
}
__device__ __forceinline__ unsigned long long pack2(float lo, float hi){
  unsigned long long r;
  asm("mov.b64 %0, {%1,%2};" : "=l"(r) : "f"(lo), "f"(hi));
  return r;
}

// ---- L2 evict_last policy loads (K stays L2-resident within a kernel) -------
__device__ __forceinline__ unsigned long long mk_policy(){
  unsigned long long p;
  asm("createpolicy.fractional.L2::evict_last.b64 %0, 1.0;" : "=l"(p));
  return p;
}
__device__ __forceinline__ uint4 ld_el4(const __half* p, unsigned long long pol){
  uint4 v;
  asm volatile("ld.global.nc.L2::cache_hint.v4.u32 {%0,%1,%2,%3}, [%4], %5;"
    : "=r"(v.x),"=r"(v.y),"=r"(v.z),"=r"(v.w) : "l"(p), "l"(pol));
  return v;
}
// coherent (L2) loads for cross-SM-communicated potentials / barrier state
__device__ __forceinline__ uint4 ld_cg4(const __half* p){
  uint4 v;
  asm volatile("ld.global.cg.v4.u32 {%0,%1,%2,%3}, [%4];"
    : "=r"(v.x),"=r"(v.y),"=r"(v.z),"=r"(v.w) : "l"(p));
  return v;
}
__device__ __forceinline__ unsigned ld_u32_cg(const unsigned* p){
  unsigned v; asm volatile("ld.global.cg.u32 %0, [%1];" : "=r"(v) : "l"(p));
  return v;
}

// ---------------- init: zero accumulators + barrier state (graph replays!) ---
__global__ void k_init(){
  int t = blockIdx.x*256 + threadIdx.x;
  for (int i=t; i<BB*NN; i += gridDim.x*256){
    d_g[i] = 0.0f;
    d_gh[i] = __ushort_as_half((unsigned short)0);
  }
  for (int i=t; i<BB*DD; i += gridDim.x*256){ d_xg[i]=0.0f; d_yg[i]=0.0f; }
  if (t < BB){ d_Lmain[t]=0.0f; d_LbX[t]=0.0f; d_LbY[t]=0.0f; }
  if (t < 16*32){ g_arr[t]=0u; g_ep[t]=0u; }
}

// ---------------- inverse row norms (one warp per row) -----------------------
__global__ void __launch_bounds__(256) k_norms(const float* __restrict__ X, const float* __restrict__ Y){
  int warp = threadIdx.x>>5, lane = threadIdx.x&31;
  int row = blockIdx.x*8 + warp;
  const float* src = blockIdx.y ? Y : X;
  float* dst = blockIdx.y ? d_iny : d_inx;
  const float* p = src + (size_t)row*DD;
  float4 a = *(const float4*)(p + lane*4);
  float4 c = *(const float4*)(p + 128 + lane*4);
  float ss = a.x*a.x+a.y*a.y+a.z*a.z+a.w*a.w
           + c.x*c.x+c.y*c.y+c.z*c.z+c.w*c.w;
  ss = warpSum(ss);
  if (lane==0) dst[row] = 1.0f / fmaxf(sqrtf(ss), 1e-12f);
}

// ------- S = Xn Yn^T -> logKh (fp16 log2-domain, row + transposed) -----------
__global__ void __launch_bounds__(256) k_gemm(const float* __restrict__ X, const float* __restrict__ Y){
  __shared__ __align__(16) unsigned long long As2[32][68];
  __shared__ __align__(16) float Bs[32][68];
  int b = blockIdx.z;
  int i0 = blockIdx.y*64, j0 = blockIdx.x*64;
  int tid = threadIdx.x;
  const float* Xp = X + ((size_t)(b*NN + i0))*DD;
  const float* Yp = Y + ((size_t)(b*NN + j0))*DD;
  int lrow = tid>>3, lk4 = (tid&7)*4;
  int tx = tid&15, ty = tid>>4;
  unsigned long long acc2[4][2];
  #pragma unroll
  for (int u=0;u<4;u++){ acc2[u][0]=0ull; acc2[u][1]=0ull; }

  for (int kc=0; kc<DD; kc+=32){
    #pragma unroll
    for (int h=0;h<2;h++){
      int r = lrow + h*32;
      float4 a = *(const float4*)(Xp + (size_t)r*DD + kc + lk4);
      *(float2*)&As2[lk4+0][r] = make_float2(a.x,a.x);
      *(float2*)&As2[lk4+1][r] = make_float2(a.y,a.y);
      *(float2*)&As2[lk4+2][r] = make_float2(a.z,a.z);
      *(float2*)&As2[lk4+3][r] = make_float2(a.w,a.w);
      float4 bv = *(const float4*)(Yp + (size_t)r*DD + kc + lk4);
      Bs[lk4+0][r]=bv.x; Bs[lk4+1][r]=bv.y; Bs[lk4+2][r]=bv.z; Bs[lk4+3][r]=bv.w;
    }
    __syncthreads();
    #pragma unroll
    for (int k=0;k<32;k++){
      unsigned long long a0 = As2[k][ty*4+0];
      unsigned long long a1 = As2[k][ty*4+1];
      unsigned long long a2 = As2[k][ty*4+2];
      unsigned long long a3 = As2[k][ty*4+3];
      unsigned long long b0 = *(const unsigned long long*)&Bs[k][tx*4];
      unsigned long long b1 = *(const unsigned long long*)&Bs[k][tx*4+2];
      fma2(acc2[0][0],a0,b0); fma2(acc2[0][1],a0,b1);
      fma2(acc2[1][0],a1,b0); fma2(acc2[1][1],a1,b1);
      fma2(acc2[2][0],a2,b0); fma2(acc2[2][1],a2,b1);
      fma2(acc2[3][0],a3,b0); fma2(acc2[3][1],a3,b1);
    }
    __syncthreads();
  }
  float acc[4][4];
  #pragma unroll
  for (int u=0;u<4;u++){
    unpack2(acc2[u][0], acc[u][0], acc[u][1]);
    unpack2(acc2[u][1], acc[u][2], acc[u][3]);
  }
  float inx[4], iny[4];
  #pragma unroll
  for (int u=0;u<4;u++){
    inx[u] = d_inx[b*NN + i0 + ty*4 + u];
    iny[u] = d_iny[b*NN + j0 + tx*4 + u];
  }
  float o[4][4];
  #pragma unroll
  for (int u=0;u<4;u++){
    int i = i0 + ty*4 + u;
    #pragma unroll
    for (int w=0;w<4;w++){
      int j = j0 + tx*4 + w;
      float S = acc[u][w]*inx[u]*iny[w];
      float q = fmaxf(1.0f - S, 0.0f);
      float pj = fabsf((float)(i-j))*(1.0f/1023.0f);
      o[u][w] = (-100.0f*q - 0.2f*pj)*L2E;    // logK * log2e
    }
    size_t off = ((size_t)(b*NN+i))*NN + j0 + tx*4;
    __half2* hp = (__half2*)(d_logKh + off);
    hp[0] = __floats2half2_rn(o[u][0], o[u][1]);
    hp[1] = __floats2half2_rn(o[u][2], o[u][3]);
  }
  // ---- transposed fp16 writes via smem staging ----
  float* tb = (float*)As2;
  __syncthreads();
  #pragma unroll
  for (int u=0;u<4;u++)
    #pragma unroll
    for (int w=0;w<4;w++)
      tb[(tx*4+w)*65 + ty*4+u] = o[u][w];
  __syncthreads();
  int jl = tid>>2, seg = tid&3;
  size_t toff = ((size_t)(b*NN + j0 + jl))*NN + i0 + seg*16;
  #pragma unroll
  for (int h=0;h<4;h++){
    float v0 = tb[jl*65 + seg*16 + h*4 + 0];
    float v1 = tb[jl*65 + seg*16 + h*4 + 1];
    float v2 = tb[jl*65 + seg*16 + h*4 + 2];
    float v3 = tb[jl*65 + seg*16 + h*4 + 3];
    __half2* hp = (__half2*)(d_logKTh + toff + h*4);
    hp[0] = __floats2half2_rn(v0, v1);
    hp[1] = __floats2half2_rn(v2, v3);
  }
}

// ---- group barrier: 64 CTAs of one batch group ------------------------------
__device__ __forceinline__ void grp_barrier(int grp, unsigned tgt){
  __syncthreads();
  if (threadIdx.x == 0){
    __threadfence();
    unsigned old = atomicAdd(&g_arr[grp*32], 1u);
    if (old == 63u){
      g_arr[grp*32] = 0u;
      __threadfence();
      atomicAdd(&g_ep[grp*32], 1u);
    } else {
      while (ld_u32_cg(&g_ep[grp*32]) < tgt) __nanosleep(32);
    }
    __threadfence();
  }
  __syncthreads();
}

// ---- one row of the sinkhorn LSE (log2 domain, packed half2) ----------------
__device__ __forceinline__ void lse_row(const __half* Mh, const __half* ph,
                                        float* outp, __half* outh,
                                        int row, int lane, unsigned long long pol){
  int b = row >> 10;
  const __half* mk = Mh + (size_t)row*NN;
  const __half* gp = ph + (size_t)b*NN;
  __half2 x[16];
  #pragma unroll
  for (int w=0;w<4;w++){
    int e = (w*32 + lane)*8;
    uint4 kv = ld_el4(mk + e, pol);
    uint4 gv = ld_cg4(gp + e);
    x[w*4+0] = __hadd2(*(__half2*)&kv.x, *(__half2*)&gv.x);
    x[w*4+1] = __hadd2(*(__half2*)&kv.y, *(__half2*)&gv.y);
    x[w*4+2] = __hadd2(*(__half2*)&kv.z, *(__half2*)&gv.z);
    x[w*4+3] = __hadd2(*(__half2*)&kv.w, *(__half2*)&gv.w);
  }
  __half2 m01 = __hmax2(x[0],x[1]),   m23 = __hmax2(x[2],x[3]);
  __half2 m45 = __hmax2(x[4],x[5]),   m67 = __hmax2(x[6],x[7]);
  __half2 m89 = __hmax2(x[8],x[9]),   mab = __hmax2(x[10],x[11]);
  __half2 mcd = __hmax2(x[12],x[13]), mef = __hmax2(x[14],x[15]);
  __half2 ma = __hmax2(__hmax2(m01,m23), __hmax2(m45,m67));
  __half2 mb = __hmax2(__hmax2(m89,mab), __hmax2(mcd,mef));
  __half2 mm = __hmax2(ma, mb);
  float Ml = fmaxf(__low2float(mm), __high2float(mm));
  float Mw = warpMax(Ml);
  __half2 M2 = __float2half2_rn(Mw);
  __half2 s0 = h2exp2(__hsub2(x[0], M2));
  __half2 s1 = h2exp2(__hsub2(x[1], M2));
  __half2 s2 = h2exp2(__hsub2(x[2], M2));
  __half2 s3 = h2exp2(__hsub2(x[3], M2));
  #pragma unroll
  for (int q=4;q<16;q+=4){
    s0 = __hadd2(s0, h2exp2(__hsub2(x[q+0], M2)));
    s1 = __hadd2(s1, h2exp2(__hsub2(x[q+1], M2)));
    s2 = __hadd2(s2, h2exp2(__hsub2(x[q+2], M2)));
    s3 = __hadd2(s3, h2exp2(__hsub2(x[q+3], M2)));
  }
  float2 f0 = __half22float2(s0), f1 = __half22float2(s1);
  float2 f2 = __half22float2(s2), f3 = __half22float2(s3);
  float S = (f0.x+f0.y) + (f1.x+f1.y) + (f2.x+f2.y) + (f3.x+f3.y);
  float Sw = warpSum(S);
  if (lane==0){
    float out = -10.0f - (Mw + __log2f(Sw));
    outp[row] = out;
    outh[row] = __float2half_rn(out);
  }
}

// ---- persistent sinkhorn: 16 independent groups of 64 CTAs ------------------
// grid=1024, __launch_bounds__(256,7): 148*7=1036 >= 1024 => all resident.
// Group g = batch g: 64 CTAs x 8 warps x 2 rows = 1024 rows/phase.
__global__ void __launch_bounds__(256, 7) k_sink(){
  int grp = blockIdx.x >> 6;
  int cta = blockIdx.x & 63;
  int w = threadIdx.x >> 5, lane = threadIdx.x & 31;
  int row0 = grp*NN + cta*16 + w*2;
  unsigned long long pol = mk_policy();
  unsigned tgt = 1u;
  for (int it=0; it<50; it++){
    lse_row(d_logKh, d_gh, d_f, d_fh, row0,   lane, pol);
    lse_row(d_logKh, d_gh, d_f, d_fh, row0+1, lane, pol);
    grp_barrier(grp, tgt++);
    lse_row(d_logKTh, d_fh, d_g, d_gh, row0,   lane, pol);
    lse_row(d_logKTh, d_fh, d_g, d_gh, row0+1, lane, pol);
    grp_barrier(grp, tgt++);
  }
}

// ---- fused marginal pass: fp16 K source, f32x2 matvec -----------------------
template<int MAIN>
__global__ void __launch_bounds__(256) k_pass(const float* __restrict__ X, const float* __restrict__ Y){
  const __half* Mh = MAIN ? d_logKh : d_logKTh;
  const float* rpp = MAIN ? d_f : d_g;
  const float* cpp = MAIN ? d_g : d_f;
  const float* V   = MAIN ? Y : X;
  const float* W   = MAIN ? X : Y;
  float* sum_out   = MAIN ? d_r : d_c;
  float* Lb_out    = MAIN ? d_LbX : d_LbY;

  __shared__ float csh[NN];
  __shared__ __align__(16) float Tsh[64][36];
  __shared__ float ssh[32];
  __shared__ float rsh[32];
  __shared__ float red[32];
  int b = blockIdx.y, i0 = blockIdx.x*32;
  int tid = threadIdx.x;
  int lane = tid&31, wp = tid>>5;
  unsigned long long pol = mk_policy();
  for (int j=tid; j<NN; j+=256) csh[j] = cpp[b*NN + j];
  if (tid<32){ ssh[tid]=0.0f; rsh[tid]=rpp[b*NN + i0 + tid]; }
  __syncthreads();
  unsigned long long acc2[16];
  #pragma unroll
  for (int r=0;r<16;r++) acc2[r]=0ull;
  float lmain = 0.0f;
  const __half* lkb = Mh + ((size_t)(b*NN + i0))*NN;
  const float* Vp  = V + ((size_t)b*NN)*DD + tid;

  for (int kc=0; kc<NN; kc+=64){
    float fv = rsh[lane];
    uint4 kv = ld_el4(lkb + (size_t)lane*NN + kc + wp*8, pol);
    float2 p0 = __half22float2(*(__half2*)&kv.x);
    float2 p1 = __half22float2(*(__half2*)&kv.y);
    float2 p2 = __half22float2(*(__half2*)&kv.z);
    float2 p3 = __half22float2(*(__half2*)&kv.w);
    float lk2[8] = {p0.x,p0.y,p1.x,p1.y,p2.x,p2.y,p3.x,p3.y};
    float rpart = 0.0f;
    #pragma unroll
    for (int u=0;u<8;u++){
      int j = kc + wp*8 + u;
      float t = exp2f(lk2[u] + fv + csh[j]);
      Tsh[wp*8+u][lane] = t;
      rpart += t;
      if (MAIN){
        float pj = fabsf((float)(i0 + lane - j))*(1.0f/1023.0f);
        lmain = fmaf(t, (-lk2[u]*LN2F - 0.2f*pj)*0.1f, lmain);
      }
    }
    atomicAdd(&ssh[lane], rpart);
    __syncthreads();
    #pragma unroll 2
    for (int k=0;k<64;k++){
      float yv = Vp[(size_t)(kc+k)*DD];
      unsigned long long yv2 = pack2(yv, yv);
      const ulonglong2* trow = (const ulonglong2*)&Tsh[k][0];
      #pragma unroll
      for (int q=0;q<8;q++){
        ulonglong2 tv = trow[q];
        fma2(acc2[2*q+0], tv.x, yv2);
        fma2(acc2[2*q+1], tv.y, yv2);
      }
    }
    __syncthreads();
  }
  if (MAIN){
    float lm = blockSum256(lmain, red);
    if (tid==0) atomicAdd(&d_Lmain[b], lm);
  }
  if (tid<32) sum_out[b*NN + i0 + tid] = ssh[tid];
  float acc[32];
  #pragma unroll
  for (int r=0;r<16;r++) unpack2(acc2[r], acc[2*r], acc[2*r+1]);
  float lb = 0.0f;
  const float* Wp = W + ((size_t)(b*NN + i0))*DD + tid;
  #pragma unroll
  for (int r=0;r<32;r++){
    float yb = acc[r] / (ssh[r] + 1e-8f);
    float diff = Wp[(size_t)r*DD] - yb;
    lb = fmaf(diff, diff, lb);
  }
  lb = blockSum256(lb, red);
  if (tid==0) atomicAdd(Lb_out + b, lb);
}

// ------------ global token: partial weighted sums (parallel) -----------------
__global__ void __launch_bounds__(256) k_gpart(const float* __restrict__ X, const float* __restrict__ Y){
  int b = blockIdx.y, i0 = blockIdx.x*128;
  int d = threadIdx.x;
  const float* Xp = X + ((size_t)(b*NN + i0))*DD + d;
  const float* Yp = Y + ((size_t)(b*NN + i0))*DD + d;
  const float* rp = d_r + b*NN + i0;
  const float* cp = d_c + b*NN + i0;
  float xg=0.0f, yg=0.0f;
  #pragma unroll 4
  for (int i=0;i<128;i++){
    xg = fmaf(Xp[(size_t)i*DD], rp[i], xg);
    yg = fmaf(Yp[(size_t)i*DD], cp[i], yg);
  }
  atomicAdd(&d_xg[b*DD+d], xg);
  atomicAdd(&d_yg[b*DD+d], yg);
}

// ------------ global cosine + per-batch loss combine -------------------------
__global__ void __launch_bounds__(256) k_gfin(){
  __shared__ float red[32];
  int b = blockIdx.x, d = threadIdx.x;
  float srp = 0.0f, scp = 0.0f;
  #pragma unroll
  for (int q=0;q<4;q++){
    srp += d_r[b*NN + q*256 + d];
    scp += d_c[b*NN + q*256 + d];
  }
  float sr = blockSum256(srp, red);
  float sc = blockSum256(scp, red);
  float xg = d_xg[b*DD+d] / (sr + 1e-8f);
  float yg = d_yg[b*DD+d] / (sc + 1e-8f);
  float ssx = blockSum256(xg*xg, red);
  float ssy = blockSum256(yg*yg, red);
  float ix = 1.0f / fmaxf(sqrtf(ssx), 1e-12f);
  float iy = 1.0f / fmaxf(sqrtf(ssy), 1e-12f);
  float dot = blockSum256((xg*ix)*(yg*iy), red);
  if (d==0){
    float lcos = 1.0f - dot;
    float lbary = (d_LbX[b] + d_LbY[b]) * (1.0f/((float)NN*(float)DD));
    d_loss[b] = d_Lmain[b] + 0.5f*lbary + 0.2f*lcos;
  }
}

__global__ void k_final(float* out){
  int t = threadIdx.x;
  float v = (t < BB) ? d_loss[t] : 0.0f;
  v = warpSum(v);
  if (t==0) out[0] = v * (1.0f/(float)BB);
}

extern "C" void kernel_launch(void* const* d_in, const int* in_sizes, int n_in,
                              void* d_out, int out_size) {
  const float* X = (const float*)d_in[0];   // eeg_embedding  (B,N,D)
  const float* Y = (const float*)d_in[1];   // text_embedding (B,N,D)
  float* out = (float*)d_out;
  (void)in_sizes; (void)n_in; (void)out_size;

  k_init<<<64, 256>>>();
  k_norms<<<dim3(BB*NN/8, 2), 256>>>(X, Y);
  k_gemm<<<dim3(NN/64, NN/64, BB), 256>>>(X, Y);
  k_sink<<<1024, 256>>>();                     // all 50 iterations, 16 groups
  k_pass<1><<<dim3(NN/32, BB), 256>>>(X, Y);   // rows: r, T@Y, L_main, LbX
  k_pass<0><<<dim3(NN/32, BB), 256>>>(X, Y);   // cols: c, T^T@X, LbY
  k_gpart<<<dim3(NN/128, BB), 256>>>(X, Y);
  k_gfin<<<BB, 256>>>();
  k_final<<<1, 32>>>(out);
}

// round 12
// speedup vs baseline: 1.0171x; 1.0171x over previous
#include <cuda_runtime.h>
#include <cuda_fp16.h>
#include <math.h>
#include <stdint.h>

#define BB 16
#define NN 1024
#define DD 256
#define L2E 1.4426950408889634f
#define LN2F 0.6931471805599453f

// fp16 array: logK * log2(e) (log2 domain) — the ONLY K storage (32 MB).
static __device__ __half d_logKh[BB*NN*NN];
// potentials in LOG2 domain
static __device__ float  d_f[BB*NN];
static __device__ float  d_g[BB*NN];
static __device__ __half d_fh[BB*NN];
static __device__ __half d_gh[BB*NN];
static __device__ float d_inx[BB*NN];
static __device__ float d_iny[BB*NN];
static __device__ float d_r[BB*NN];
static __device__ float d_c[BB*NN];
static __device__ float d_xg[BB*DD];
static __device__ float d_yg[BB*DD];
static __device__ float d_Lmain[BB];
static __device__ float d_LbX[BB];
static __device__ float d_LbY[BB];
static __device__ float d_loss[BB];

__device__ __forceinline__ float warpMax(float v){
  #pragma unroll
  for (int o=16;o>0;o>>=1) v = fmaxf(v, __shfl_xor_sync(0xffffffffu, v, o));
  return v;
}
__device__ __forceinline__ float warpSum(float v){
  #pragma unroll
  for (int o=16;o>0;o>>=1) v += __shfl_xor_sync(0xffffffffu, v, o);
  return v;
}
__device__ __forceinline__ float blockSum256(float v, float* sm){
  __syncthreads();
  v = warpSum(v);
  int w = threadIdx.x>>5, l = threadIdx.x&31;
  if (l==0) sm[w]=v;
  __syncthreads();
  if (w==0){
    float t = (l<8)? sm[l] : 0.0f;
    t = warpSum(t);
    if (l==0) sm[0]=t;
  }
  __syncthreads();
  return sm[0];
}

__device__ __forceinline__ void fma2(unsigned long long& d, unsigned long long a, unsigned long long b){
  asm("fma.rn.f32x2 %0, %1, %2, %0;" : "+l"(d) : "l"(a), "l"(b));
}
__device__ __forceinline__ void unpack2(unsigned long long p, float& lo, float& hi){
  asm("mov.b64 {%0,%1}, %2;" : "=f"(lo), "=f"(hi) : "l"(p));
}
__device__ __forceinline__ unsigned long long pack2(float lo, float hi){
  unsigned long long r;
  asm("mov.b64 %0, {%1,%2};" : "=l"(r) : "f"(lo), "f"(hi));
  return r;
}

__device__ __forceinline__ unsigned long long mk_policy(){
  unsigned long long p;
  asm("createpolicy.fractional.L2::evict_last.b64 %0, 1.0;" : "=l"(p));
  return p;
}
__device__ __forceinline__ uint4 ld_el4(const __half* p, unsigned long long pol){
  uint4 v;
  asm volatile("ld.global.nc.L2::cache_hint.v4.u32 {%0,%1,%2,%3}, [%4], %5;"
    : "=r"(v.x),"=r"(v.y),"=r"(v.z),"=r"(v.w) : "l"(p), "l"(pol));
  return v;
}

// ---------------- init: zero accumulators (graph replays!) -------------------
__global__ void k_init(){
  int t = blockIdx.x*256 + threadIdx.x;
  for (int i=t; i<BB*NN; i += gridDim.x*256){
    d_g[i] = 0.0f;
    d_gh[i] = __ushort_as_half((unsigned short)0);
  }
  for (int i=t; i<BB*DD; i += gridDim.x*256){ d_xg[i]=0.0f; d_yg[i]=0.0f; }
  if (t < BB){ d_Lmain[t]=0.0f; d_LbX[t]=0.0f; d_LbY[t]=0.0f; }
}

// ---------------- inverse row norms (one warp per row) -----------------------
__global__ void __launch_bounds__(256) k_norms(const float* __restrict__ X, const float* __restrict__ Y){
  int warp = threadIdx.x>>5, lane = threadIdx.x&31;
  int row = blockIdx.x*8 + warp;
  const float* src = blockIdx.y ? Y : X;
  float* dst = blockIdx.y ? d_iny : d_inx;
  const float* p = src + (size_t)row*DD;
  float4 a = *(const float4*)(p + lane*4);
  float4 c = *(const float4*)(p + 128 + lane*4);
  float ss = a.x*a.x+a.y*a.y+a.z*a.z+a.w*a.w
           + c.x*c.x+c.y*c.y+c.z*c.z+c.w*c.w;
  ss = warpSum(ss);
  if (lane==0) dst[row] = 1.0f / fmaxf(sqrtf(ss), 1e-12f);
}

// ------- S = Xn Yn^T -> logKh (fp16 log2-domain, row-major ONLY) -------------
__global__ void __launch_bounds__(256) k_gemm(const float* __restrict__ X, const float* __restrict__ Y){
  __shared__ __align__(16) unsigned long long As2[32][68];
  __shared__ __align__(16) float Bs[32][68];
  int b = blockIdx.z;
  int i0 = blockIdx.y*64, j0 = blockIdx.x*64;
  int tid = threadIdx.x;
  const float* Xp = X + ((size_t)(b*NN + i0))*DD;
  const float* Yp = Y + ((size_t)(b*NN + j0))*DD;
  int lrow = tid>>3, lk4 = (tid&7)*4;
  int tx = tid&15, ty = tid>>4;
  unsigned long long acc2[4][2];
  #pragma unroll
  for (int u=0;u<4;u++){ acc2[u][0]=0ull; acc2[u][1]=0ull; }

  for (int kc=0; kc<DD; kc+=32){
    #pragma unroll
    for (int h=0;h<2;h++){
      int r = lrow + h*32;
      float4 a = *(const float4*)(Xp + (size_t)r*DD + kc + lk4);
      *(float2*)&As2[lk4+0][r] = make_float2(a.x,a.x);
      *(float2*)&As2[lk4+1][r] = make_float2(a.y,a.y);
      *(float2*)&As2[lk4+2][r] = make_float2(a.z,a.z);
      *(float2*)&As2[lk4+3][r] = make_float2(a.w,a.w);
      float4 bv = *(const float4*)(Yp + (size_t)r*DD + kc + lk4);
      Bs[lk4+0][r]=bv.x; Bs[lk4+1][r]=bv.y; Bs[lk4+2][r]=bv.z; Bs[lk4+3][r]=bv.w;
    }
    __syncthreads();
    #pragma unroll
    for (int k=0;k<32;k++){
      unsigned long long a0 = As2[k][ty*4+0];
      unsigned long long a1 = As2[k][ty*4+1];
      unsigned long long a2 = As2[k][ty*4+2];
      unsigned long long a3 = As2[k][ty*4+3];
      unsigned long long b0 = *(const unsigned long long*)&Bs[k][tx*4];
      unsigned long long b1 = *(const unsigned long long*)&Bs[k][tx*4+2];
      fma2(acc2[0][0],a0,b0); fma2(acc2[0][1],a0,b1);
      fma2(acc2[1][0],a1,b0); fma2(acc2[1][1],a1,b1);
      fma2(acc2[2][0],a2,b0); fma2(acc2[2][1],a2,b1);
      fma2(acc2[3][0],a3,b0); fma2(acc2[3][1],a3,b1);
    }
    __syncthreads();
  }
  float acc[4][4];
  #pragma unroll
  for (int u=0;u<4;u++){
    unpack2(acc2[u][0], acc[u][0], acc[u][1]);
    unpack2(acc2[u][1], acc[u][2], acc[u][3]);
  }
  float inx[4], iny[4];
  #pragma unroll
  for (int u=0;u<4;u++){
    inx[u] = d_inx[b*NN + i0 + ty*4 + u];
    iny[u] = d_iny[b*NN + j0 + tx*4 + u];
  }
  #pragma unroll
  for (int u=0;u<4;u++){
    int i = i0 + ty*4 + u;
    float o[4];
    #pragma unroll
    for (int w=0;w<4;w++){
      int j = j0 + tx*4 + w;
      float S = acc[u][w]*inx[u]*iny[w];
      float q = fmaxf(1.0f - S, 0.0f);
      float pj = fabsf((float)(i-j))*(1.0f/1023.0f);
      o[w] = (-100.0f*q - 0.2f*pj)*L2E;       // logK * log2e
    }
    size_t off = ((size_t)(b*NN+i))*NN + j0 + tx*4;
    __half2* hp = (__half2*)(d_logKh + off);
    hp[0] = __floats2half2_rn(o[0], o[1]);
    hp[1] = __floats2half2_rn(o[2], o[3]);
  }
}

// ---- f-update: warp-per-row over Kh (row-major), packed half2, 2-phase ------
__global__ void __launch_bounds__(256) k_lsef(){
  int warp = threadIdx.x>>5, lane = threadIdx.x&31;
  int row = blockIdx.x*8 + warp;
  int b = row >> 10;
  const __half* mk = d_logKh + (size_t)row*NN;
  const uint4* gk = (const uint4*)(d_gh + (size_t)b*NN);
  unsigned long long pol = mk_policy();
  __half2 x[16];
  #pragma unroll
  for (int w=0;w<4;w++){
    int idx = w*32 + lane;
    uint4 kv = ld_el4(mk + idx*8, pol);
    uint4 gv = gk[idx];
    x[w*4+0] = __hadd2(*(__half2*)&kv.x, *(__half2*)&gv.x);
    x[w*4+1] = __hadd2(*(__half2*)&kv.y, *(__half2*)&gv.y);
    x[w*4+2] = __hadd2(*(__half2*)&kv.z, *(__half2*)&gv.z);
    x[w*4+3] = __hadd2(*(__half2*)&kv.w, *(__half2*)&gv.w);
  }
  __half2 m01 = __hmax2(x[0],x[1]),   m23 = __hmax2(x[2],x[3]);
  __half2 m45 = __hmax2(x[4],x[5]),   m67 = __hmax2(x[6],x[7]);
  __half2 m89 = __hmax2(x[8],x[9]),   mab = __hmax2(x[10],x[11]);
  __half2 mcd = __hmax2(x[12],x[13]), mef = __hmax2(x[14],x[15]);
  __half2 ma = __hmax2(__hmax2(m01,m23), __hmax2(m45,m67));
  __half2 mb = __hmax2(__hmax2(m89,mab), __hmax2(mcd,mef));
  __half2 mm = __hmax2(ma, mb);
  float Ml = fmaxf(__low2float(mm), __high2float(mm));
  float Mw = warpMax(Ml);
  __half2 M2 = __float2half2_rn(Mw);
  __half2 s0 = h2exp2(__hsub2(x[0], M2));
  __half2 s1 = h2exp2(__hsub2(x[1], M2));
  __half2 s2 = h2exp2(__hsub2(x[2], M2));
  __half2 s3 = h2exp2(__hsub2(x[3], M2));
  #pragma unroll
  for (int q=4;q<16;q+=4){
    s0 = __hadd2(s0, h2exp2(__hsub2(x[q+0], M2)));
    s1 = __hadd2(s1, h2exp2(__hsub2(x[q+1], M2)));
    s2 = __hadd2(s2, h2exp2(__hsub2(x[q+2], M2)));
    s3 = __hadd2(s3, h2exp2(__hsub2(x[q+3], M2)));
  }
  float2 f0 = __half22float2(s0), f1 = __half22float2(s1);
  float2 f2 = __half22float2(s2), f3 = __half22float2(s3);
  float S = (f0.x+f0.y) + (f1.x+f1.y) + (f2.x+f2.y) + (f3.x+f3.y);
  float Sw = warpSum(S);
  if (lane==0){
    float out = -10.0f - (Mw + __log2f(Sw));
    d_f[row] = out;
    d_fh[row] = __float2half_rn(out);
  }
}

// ---- g-update from ROW-MAJOR Kh: column LSE, chunked two-phase --------------
// grid (NN/64, BB), 512 threads. Warp w: rows w*64..w*64+63.
// lane: ro=lane>>3 (row-in-quad), cg=lane&7 (8 columns: j0+cg*8..+8).
__global__ void __launch_bounds__(512) k_lseg(){
  __shared__ float fsh[NN];
  __shared__ __half2 smM[16][8][4];
  __shared__ __half2 smS[16][8][4];
  int b = blockIdx.y, j0 = blockIdx.x*64;
  int tid = threadIdx.x;
  int w = tid>>5, lane = tid&31;
  int ro = lane>>3, cg = lane&7;
  for (int i=tid; i<NN; i+=512) fsh[i] = d_f[b*NN + i];
  __syncthreads();
  const __half* base = d_logKh + (size_t)b*NN*NN + j0 + cg*8;
  unsigned long long pol = mk_policy();
  __half2 M[4], S[4];
  // ---- chunk 0 (rows t=0..7 of this lane's 16) ----
  {
    __half2 xb[8][4];
    #pragma unroll
    for (int t=0;t<8;t++){
      int row = w*64 + t*4 + ro;
      uint4 kv = ld_el4(base + (size_t)row*NN, pol);
      __half2 fr = __float2half2_rn(fsh[row]);
      xb[t][0] = __hadd2(*(__half2*)&kv.x, fr);
      xb[t][1] = __hadd2(*(__half2*)&kv.y, fr);
      xb[t][2] = __hadd2(*(__half2*)&kv.z, fr);
      xb[t][3] = __hadd2(*(__half2*)&kv.w, fr);
    }
    #pragma unroll
    for (int q=0;q<4;q++){
      __half2 m = xb[0][q];
      #pragma unroll
      for (int t=1;t<8;t++) m = __hmax2(m, xb[t][q]);
      __half2 s = h2exp2(__hsub2(xb[0][q], m));
      #pragma unroll
      for (int t=1;t<8;t++) s = __hadd2(s, h2exp2(__hsub2(xb[t][q], m)));
      M[q]=m; S[q]=s;
    }
  }
  // ---- chunk 1 (rows t=8..15) + merge ----
  {
    __half2 xb[8][4];
    #pragma unroll
    for (int t=0;t<8;t++){
      int row = w*64 + (t+8)*4 + ro;
      uint4 kv = ld_el4(base + (size_t)row*NN, pol);
      __half2 fr = __float2half2_rn(fsh[row]);
      xb[t][0] = __hadd2(*(__half2*)&kv.x, fr);
      xb[t][1] = __hadd2(*(__half2*)&kv.y, fr);
      xb[t][2] = __hadd2(*(__half2*)&kv.z, fr);
      xb[t][3] = __hadd2(*(__half2*)&kv.w, fr);
    }
    #pragma unroll
    for (int q=0;q<4;q++){
      __half2 m = xb[0][q];
      #pragma unroll
      for (int t=1;t<8;t++) m = __hmax2(m, xb[t][q]);
      __half2 s = h2exp2(__hsub2(xb[0][q], m));
      #pragma unroll
      for (int t=1;t<8;t++) s = __hadd2(s, h2exp2(__hsub2(xb[t][q], m)));
      __half2 Mn = __hmax2(M[q], m);
      S[q] = __hadd2(__hmul2(S[q], h2exp2(__hsub2(M[q],Mn))),
                     __hmul2(s,    h2exp2(__hsub2(m,   Mn))));
      M[q] = Mn;
    }
  }
  // ---- cross-lane merge over row-offsets (xor 8, xor 16) ----
  #pragma unroll
  for (int off=8; off<=16; off<<=1){
    #pragma unroll
    for (int q=0;q<4;q++){
      __half2 Mo = __shfl_xor_sync(0xffffffffu, M[q], off);
      __half2 So = __shfl_xor_sync(0xffffffffu, S[q], off);
      __half2 Mn = __hmax2(M[q], Mo);
      S[q] = __hadd2(__hmul2(S[q], h2exp2(__hsub2(M[q],Mn))),
                     __hmul2(So,   h2exp2(__hsub2(Mo,  Mn))));
      M[q] = Mn;
    }
  }
  if (ro==0){
    #pragma unroll
    for (int q=0;q<4;q++){ smM[w][cg][q]=M[q]; smS[w][cg][q]=S[q]; }
  }
  __syncthreads();
  // ---- final: one thread per column, fp32 merge over 16 warps ----
  if (tid < 64){
    int jj = tid;
    int cg2 = jj>>3, q2 = (jj&7)>>1, hi = jj&1;
    float mv[16], sv[16];
    float Mf = -1e30f;
    #pragma unroll
    for (int ww=0;ww<16;ww++){
      __half2 mh = smM[ww][cg2][q2];
      __half2 sh = smS[ww][cg2][q2];
      float m = hi ? __high2float(mh) : __low2float(mh);
      float s = hi ? __high2float(sh) : __low2float(sh);
      mv[ww]=m; sv[ww]=s;
      Mf = fmaxf(Mf, m);
    }
    float Sf = 0.0f;
    #pragma unroll
    for (int ww=0;ww<16;ww++) Sf += sv[ww]*exp2f(mv[ww]-Mf);
    float out = -10.0f - (Mf + __log2f(Sf));
    d_g[b*NN + j0 + jj] = out;
    d_gh[b*NN + j0 + jj] = __float2half_rn(out);
  }
}

// ---- row pass (MAIN): r_i, T@Y, L_main, sum(X-Y_bar)^2 ----------------------
__global__ void __launch_bounds__(256) k_pass1(const float* __restrict__ X, const float* __restrict__ Y){
  __shared__ float csh[NN];
  __shared__ __align__(16) float Tsh[64][36];
  __shared__ float ssh[32];
  __shared__ float rsh[32];
  __shared__ float red[32];
  int b = blockIdx.y, i0 = blockIdx.x*32;
  int tid = threadIdx.x;
  int lane = tid&31, wp = tid>>5;
  unsigned long long pol = mk_policy();
  for (int j=tid; j<NN; j+=256) csh[j] = d_g[b*NN + j];
  if (tid<32){ ssh[tid]=0.0f; rsh[tid]=d_f[b*NN + i0 + tid]; }
  __syncthreads();
  unsigned long long acc2[16];
  #pragma unroll
  for (int r=0;r<16;r++) acc2[r]=0ull;
  float lmain = 0.0f;
  const __half* lkb = d_logKh + ((size_t)(b*NN + i0))*NN;
  const float* Vp  = Y + ((size_t)b*NN)*DD + tid;

  for (int kc=0; kc<NN; kc+=64){
    float fv = rsh[lane];
    uint4 kv = ld_el4(lkb + (size_t)lane*NN + kc + wp*8, pol);
    float2 p0 = __half22float2(*(__half2*)&kv.x);
    float2 p1 = __half22float2(*(__half2*)&kv.y);
    float2 p2 = __half22float2(*(__half2*)&kv.z);
    float2 p3 = __half22float2(*(__half2*)&kv.w);
    float lk2[8] = {p0.x,p0.y,p1.x,p1.y,p2.x,p2.y,p3.x,p3.y};
    float rpart = 0.0f;
    #pragma unroll
    for (int u=0;u<8;u++){
      int j = kc + wp*8 + u;
      float t = exp2f(lk2[u] + fv + csh[j]);
      Tsh[wp*8+u][lane] = t;
      rpart += t;
      float pj = fabsf((float)(i0 + lane - j))*(1.0f/1023.0f);
      lmain = fmaf(t, (-lk2[u]*LN2F - 0.2f*pj)*0.1f, lmain);
    }
    atomicAdd(&ssh[lane], rpart);
    __syncthreads();
    #pragma unroll 2
    for (int k=0;k<64;k++){
      float yv = Vp[(size_t)(kc+k)*DD];
      unsigned long long yv2 = pack2(yv, yv);
      const ulonglong2* trow = (const ulonglong2*)&Tsh[k][0];
      #pragma unroll
      for (int q=0;q<8;q++){
        ulonglong2 tv = trow[q];
        fma2(acc2[2*q+0], tv.x, yv2);
        fma2(acc2[2*q+1], tv.y, yv2);
      }
    }
    __syncthreads();
  }
  float lm = blockSum256(lmain, red);
  if (tid==0) atomicAdd(&d_Lmain[b], lm);
  if (tid<32) d_r[b*NN + i0 + tid] = ssh[tid];
  float acc[32];
  #pragma unroll
  for (int r=0;r<16;r++) unpack2(acc2[r], acc[2*r], acc[2*r+1]);
  float lb = 0.0f;
  const float* Wp = X + ((size_t)(b*NN + i0))*DD + tid;
  #pragma unroll
  for (int r=0;r<32;r++){
    float yb = acc[r] / (ssh[r] + 1e-8f);
    float diff = Wp[(size_t)r*DD] - yb;
    lb = fmaf(diff, diff, lb);
  }
  lb = blockSum256(lb, red);
  if (tid==0) atomicAdd(&d_LbX[b], lb);
}

// ---- column pass from ROW-MAJOR Kh: c_j, T^T@X, sum(Y-X_bar)^2 --------------
// Tile = 32 columns (pass-rows = j). Warp wp generates K rows kc+wp*8..+8.
__global__ void __launch_bounds__(256) k_passT(const float* __restrict__ X, const float* __restrict__ Y){
  __shared__ float csh[NN];                  // f over i
  __shared__ __align__(16) float Tsh[64][36];
  __shared__ float ssh[32];                  // c_j
  __shared__ float rsh[32];                  // g[j0..j0+31]
  __shared__ float red[32];
  int b = blockIdx.y, j0 = blockIdx.x*32;
  int tid = threadIdx.x;
  int lane = tid&31, wp = tid>>5;
  int half = lane>>4, cp = lane&15;          // row-select, column-pair
  for (int i=tid; i<NN; i+=256) csh[i] = d_f[b*NN + i];
  if (tid<32){ ssh[tid]=0.0f; rsh[tid]=d_g[b*NN + j0 + tid]; }
  __syncthreads();
  unsigned long long acc2[16];
  #pragma unroll
  for (int r=0;r<16;r++) acc2[r]=0ull;
  float csum0 = 0.0f, csum1 = 0.0f;
  const __half* kb = d_logKh + (size_t)b*NN*NN + j0 + cp*2;
  const float* Vp  = X + ((size_t)b*NN)*DD + tid;
  float gj0 = rsh[cp*2], gj1 = rsh[cp*2+1];

  for (int kc=0; kc<NN; kc+=64){
    #pragma unroll
    for (int v=0; v<4; v++){
      int i = kc + wp*8 + v*2 + half;
      __half2 kv = *(const __half2*)(kb + (size_t)i*NN);
      float2 kf = __half22float2(kv);
      float fi = csh[i];
      float t0 = exp2f(kf.x + fi + gj0);
      float t1 = exp2f(kf.y + fi + gj1);
      csum0 += t0; csum1 += t1;
      *(float2*)&Tsh[wp*8 + v*2 + half][cp*2] = make_float2(t0, t1);
    }
    __syncthreads();
    #pragma unroll 2
    for (int k=0;k<64;k++){
      float xv = Vp[(size_t)(kc+k)*DD];
      unsigned long long xv2 = pack2(xv, xv);
      const ulonglong2* trow = (const ulonglong2*)&Tsh[k][0];
      #pragma unroll
      for (int q=0;q<8;q++){
        ulonglong2 tv = trow[q];
        fma2(acc2[2*q+0], tv.x, xv2);
        fma2(acc2[2*q+1], tv.y, xv2);
      }
    }
    __syncthreads();
  }
  // fold the two row-halves, then 8 warps accumulate column sums
  csum0 += __shfl_xor_sync(0xffffffffu, csum0, 16);
  csum1 += __shfl_xor_sync(0xffffffffu, csum1, 16);
  if (half==0){
    atomicAdd(&ssh[cp*2+0], csum0);
    atomicAdd(&ssh[cp*2+1], csum1);
  }
  __syncthreads();
  if (tid<32) d_c[b*NN + j0 + tid] = ssh[tid];
  float acc[32];
  #pragma unroll
  for (int r=0;r<16;r++) unpack2(acc2[r], acc[2*r], acc[2*r+1]);
  float lb = 0.0f;
  const float* Wp = Y + ((size_t)(b*NN + j0))*DD + tid;
  #pragma unroll
  for (int r=0;r<32;r++){
    float xb = acc[r] / (ssh[r] + 1e-8f);
    float diff = Wp[(size_t)r*DD] - xb;
    lb = fmaf(diff, diff, lb);
  }
  lb = blockSum256(lb, red);
  if (tid==0) atomicAdd(&d_LbY[b], lb);
}

// ------------ global token: partial weighted sums (parallel) -----------------
__global__ void __launch_bounds__(256) k_gpart(const float* __restrict__ X, const float* __restrict__ Y){
  int b = blockIdx.y, i0 = blockIdx.x*128;
  int d = threadIdx.x;
  const float* Xp = X + ((size_t)(b*NN + i0))*DD + d;
  const float* Yp = Y + ((size_t)(b*NN + i0))*DD + d;
  const float* rp = d_r + b*NN + i0;
  const float* cp = d_c + b*NN + i0;
  float xg=0.0f, yg=0.0f;
  #pragma unroll 4
  for (int i=0;i<128;i++){
    xg = fmaf(Xp[(size_t)i*DD], rp[i], xg);
    yg = fmaf(Yp[(size_t)i*DD], cp[i], yg);
  }
  atomicAdd(&d_xg[b*DD+d], xg);
  atomicAdd(&d_yg[b*DD+d], yg);
}

// ------------ global cosine + per-batch loss combine -------------------------
__global__ void __launch_bounds__(256) k_gfin(){
  __shared__ float red[32];
  int b = blockIdx.x, d = threadIdx.x;
  float srp = 0.0f, scp = 0.0f;
  #pragma unroll
  for (int q=0;q<4;q++){
    srp += d_r[b*NN + q*256 + d];
    scp += d_c[b*NN + q*256 + d];
  }
  float sr = blockSum256(srp, red);
  float sc = blockSum256(scp, red);
  float xg = d_xg[b*DD+d] / (sr + 1e-8f);
  float yg = d_yg[b*DD+d] / (sc + 1e-8f);
  float ssx = blockSum256(xg*xg, red);
  float ssy = blockSum256(yg*yg, red);
  float ix = 1.0f / fmaxf(sqrtf(ssx), 1e-12f);
  float iy = 1.0f / fmaxf(sqrtf(ssy), 1e-12f);
  float dot = blockSum256((xg*ix)*(yg*iy), red);
  if (d==0){
    float lcos = 1.0f - dot;
    float lbary = (d_LbX[b] + d_LbY[b]) * (1.0f/((float)NN*(float)DD));
    d_loss[b] = d_Lmain[b] + 0.5f*lbary + 0.2f*lcos;
  }
}

__global__ void k_final(float* out){
  int t = threadIdx.x;
  float v = (t < BB) ? d_loss[t] : 0.0f;
  v = warpSum(v);
  if (t==0) out[0] = v * (1.0f/(float)BB);
}

extern "C" void kernel_launch(void* const* d_in, const int* in_sizes, int n_in,
                              void* d_out, int out_size) {
  const float* X = (const float*)d_in[0];   // eeg_embedding  (B,N,D)
  const float* Y = (const float*)d_in[1];   // text_embedding (B,N,D)
  float* out = (float*)d_out;
  (void)in_sizes; (void)n_in; (void)out_size;

  k_init<<<64, 256>>>();
  k_norms<<<dim3(BB*NN/8, 2), 256>>>(X, Y);
  k_gemm<<<dim3(NN/64, NN/64, BB), 256>>>(X, Y);
  for (int it=0; it<50; it++){
    k_lsef<<<BB*NN/8, 256>>>();             // f from Kh rows + g
    k_lseg<<<dim3(NN/64, BB), 512>>>();     // g from Kh cols + f
  }
  k_pass1<<<dim3(NN/32, BB), 256>>>(X, Y);  // rows: r, T@Y, L_main, LbX
  k_passT<<<dim3(NN/32, BB), 256>>>(X, Y);  // cols: c, T^T@X, LbY
  k_gpart<<<dim3(NN/128, BB), 256>>>(X, Y);
  k_gfin<<<BB, 256>>>();
  k_final<<<1, 32>>>(out);
}